// round 5
// baseline (speedup 1.0000x reference)
#include <cuda_runtime.h>
#include <cuda_bf16.h>
#include <math.h>
#include <stdint.h>

// Problem constants
#define NB 8
#define NC 256
#define NHW 1024
#define NROW 8192              // NB*NHW
#define INV_T 10.0f            // 1/TEMPERATURE
#define POS_COUNT 8388608.0    // 8192*1024

// ---------------- device scratch (no allocation allowed) ----------------
__device__ __align__(256) __nv_bfloat16 g_Rn[NROW * NC];   // normalized rgb
__device__ __align__(256) __nv_bfloat16 g_Xn[NROW * NC];   // normalized x
__device__ float  g_Xsum[8 * NC];           // per-class (j%8) column sums of normalized x
__device__ float  g_rowsum[NROW];           // sum_j exp(sim_ij)
__device__ double g_acc;                    // global loss accumulator

__device__ __forceinline__ float ex2f(float x) {
    float r; asm("ex2.approx.f32 %0, %1;" : "=f"(r) : "f"(x)); return r;
}

// ---------------- init ---------------------------------------------------
__global__ void k_init() {
    int idx = blockIdx.x * blockDim.x + threadIdx.x;
    if (idx < NROW) g_rowsum[idx] = 0.0f;
    if (idx < 8 * NC) g_Xsum[idx] = 0.0f;
    if (idx == 0) g_acc = 0.0;
}

// ---------------- normalize (B,C,H,W) -> rows of 256, bf16 --------------
// grid 512: blocks [0,256) process rgb, [256,512) process x.
__global__ void __launch_bounds__(256) k_norm(const float* __restrict__ rgb,
                                              const float* __restrict__ x) {
    __shared__ float s[32][257];
    __shared__ float ps[8][32];
    __shared__ float invs[32];

    int tid = threadIdx.x;
    int isX = blockIdx.x >> 8;
    int bix = blockIdx.x & 255;
    int b   = bix >> 5;
    int p0  = (bix & 31) << 5;
    int pl  = tid & 31;
    int cg  = tid >> 5;

    const float* in = isX ? x : rgb;
    const float* base = in + (size_t)b * NC * NHW + p0;
    #pragma unroll
    for (int co = 0; co < 32; ++co) {
        int c = co * 8 + cg;
        s[pl][c] = base[(size_t)c * NHW + pl];
    }
    __syncthreads();

    float part = 0.0f;
    #pragma unroll
    for (int k = 0; k < 32; ++k) {
        float v = s[pl][cg * 32 + k];
        part = fmaf(v, v, part);
    }
    ps[cg][pl] = part;
    __syncthreads();

    if (tid < 32) {
        float ss = 0.0f;
        #pragma unroll
        for (int j = 0; j < 8; ++j) ss += ps[j][tid];
        invs[tid] = 1.0f / fmaxf(sqrtf(ss), 1e-12f);
    }
    __syncthreads();

    __nv_bfloat16* out = isX ? g_Xn : g_Rn;
    float xacc[8];
    #pragma unroll
    for (int m = 0; m < 8; ++m) xacc[m] = 0.0f;

    #pragma unroll
    for (int rl = 0; rl < 32; ++rl) {
        float v = s[rl][tid] * invs[rl];
        out[(size_t)(b * NHW + p0 + rl) * NC + tid] = __float2bfloat16(v);
        xacc[rl & 7] += v;
    }
    if (isX) {
        #pragma unroll
        for (int m = 0; m < 8; ++m)
            atomicAdd(&g_Xsum[m * NC + tid], xacc[m]);
    }
}

// ---------------- helpers for the GEMM ----------------------------------
__device__ __forceinline__ void mma16816(float c[4], const uint32_t a[4],
                                         uint32_t b0, uint32_t b1) {
    asm volatile(
        "mma.sync.aligned.m16n8k16.row.col.f32.bf16.bf16.f32 "
        "{%0,%1,%2,%3}, {%4,%5,%6,%7}, {%8,%9}, {%0,%1,%2,%3};"
        : "+f"(c[0]), "+f"(c[1]), "+f"(c[2]), "+f"(c[3])
        : "r"(a[0]), "r"(a[1]), "r"(a[2]), "r"(a[3]), "r"(b0), "r"(b1));
}

// issue 32x256 bf16 tile load (16KB) via cp.async, one commit group
__device__ __forceinline__ void issue_load(uint32_t dst_base,
                                           const __nv_bfloat16* src_base,
                                           int w, int lane) {
    const char* src = (const char*)src_base + lane * 16;
    #pragma unroll
    for (int it = 0; it < 4; ++it) {
        int row = it * 8 + w;
        uint32_t dst = dst_base + (uint32_t)(row * 132 + lane * 4) * 4;
        asm volatile("cp.async.cg.shared.global [%0], [%1], 16;"
                     :: "r"(dst), "l"(src + (size_t)row * 512) : "memory");
    }
    asm volatile("cp.async.commit_group;" ::: "memory");
}

// ---------------- fused GEMM + exp row-sum ------------------------------
// 512 blocks: 64 row-blocks (128 rows) x 8 column slices (1024 cols).
// Per CTA: 32 B-tiles of 32 cols, 3-stage cp.async pipeline (1 sync/tile).
// 8 warps; warp owns 16 rows; A register-resident for full K=256.
// 2 CTAs/SM for latency hiding (regs capped at 128).
__global__ void __launch_bounds__(256, 2) k_gemm() {
    extern __shared__ uint32_t Xs[];   // 3 buffers of 32*132 words

    int tid  = threadIdx.x;
    int w    = tid >> 5;
    int lane = tid & 31;
    int g    = lane >> 2;
    int tig  = lane & 3;

    int rowBlk = blockIdx.x & 63;
    int cslice = blockIdx.x >> 6;          // 0..7
    int r0     = rowBlk * 128;
    int cstart = cslice * 1024;

    int rg = r0 + w * 16 + g;
    const __nv_bfloat16* Ra = g_Rn + (size_t)rg * NC;
    const __nv_bfloat16* Rb = g_Rn + (size_t)(rg + 8) * NC;

    // A fragments for full K=256
    uint32_t a[16][4];
    #pragma unroll
    for (int kc = 0; kc < 16; ++kc) {
        a[kc][0] = *(const uint32_t*)(Ra + kc * 16 + 2 * tig);
        a[kc][1] = *(const uint32_t*)(Rb + kc * 16 + 2 * tig);
        a[kc][2] = *(const uint32_t*)(Ra + kc * 16 + 8 + 2 * tig);
        a[kc][3] = *(const uint32_t*)(Rb + kc * 16 + 8 + 2 * tig);
    }

    // ldmatrix per-lane offset (q=0, kc=0), in words
    int mi = lane >> 3, rr = lane & 7;
    int ldsm_off = (((mi >> 1) * 8) + rr) * 132 + (mi & 1) * 4;

    uint32_t sbase = (uint32_t)__cvta_generic_to_shared(Xs);
    const uint32_t BUFW = 32u * 132u * 4u;

    float rs0 = 0.0f, rs1 = 0.0f;
    const float S = 14.426950408889634f;   // log2(e)/0.1

    const __nv_bfloat16* xb = g_Xn + (size_t)cstart * NC;
    issue_load(sbase,        xb,            w, lane);
    issue_load(sbase + BUFW, xb + 32 * NC,  w, lane);

    #pragma unroll 1
    for (int nt = 0; nt < 32; ++nt) {
        if (nt < 31) {
            asm volatile("cp.async.wait_group 1;" ::: "memory");
        } else {
            asm volatile("cp.async.wait_group 0;" ::: "memory");
        }
        __syncthreads();   // all warps done with iter nt-1; buf (nt+2)%3 free; buf nt%3 visible
        if (nt + 2 < 32)
            issue_load(sbase + (uint32_t)((nt + 2) % 3) * BUFW, xb + (size_t)(nt + 2) * 32 * NC, w, lane);

        float c[4][4];
        #pragma unroll
        for (int n8 = 0; n8 < 4; ++n8) {
            c[n8][0] = 0.f; c[n8][1] = 0.f; c[n8][2] = 0.f; c[n8][3] = 0.f;
        }

        uint32_t ld_base = sbase + (uint32_t)(nt % 3) * BUFW + (uint32_t)ldsm_off * 4;
        #pragma unroll
        for (int kc = 0; kc < 16; ++kc) {
            #pragma unroll
            for (int q = 0; q < 2; ++q) {
                uint32_t b0, b1, b2, b3;
                uint32_t ad = ld_base + (uint32_t)(q * 2112 + kc * 8) * 4;
                asm volatile(
                    "ldmatrix.sync.aligned.m8n8.x4.shared.b16 {%0,%1,%2,%3}, [%4];"
                    : "=r"(b0), "=r"(b1), "=r"(b2), "=r"(b3) : "r"(ad));
                mma16816(c[2 * q],     a[kc], b0, b1);
                mma16816(c[2 * q + 1], a[kc], b2, b3);
            }
        }

        #pragma unroll
        for (int n8 = 0; n8 < 4; ++n8) {
            rs0 += ex2f(c[n8][0] * S) + ex2f(c[n8][1] * S);
            rs1 += ex2f(c[n8][2] * S) + ex2f(c[n8][3] * S);
        }
    }

    rs0 += __shfl_xor_sync(0xffffffffu, rs0, 1);
    rs0 += __shfl_xor_sync(0xffffffffu, rs0, 2);
    rs1 += __shfl_xor_sync(0xffffffffu, rs1, 1);
    rs1 += __shfl_xor_sync(0xffffffffu, rs1, 2);
    if (tig == 0) {
        atomicAdd(&g_rowsum[rg], rs0);
        atomicAdd(&g_rowsum[rg + 8], rs1);
    }
}

// ---------------- per-row: 1024*log(rowsum) - posdot/T ------------------
// warp per row; lane loads 8 bf16 of R (one uint4) and 8 floats of Xsum.
__global__ void __launch_bounds__(256) k_row() {
    int tid  = threadIdx.x;
    int lane = tid & 31;
    int w    = tid >> 5;
    int row  = blockIdx.x * 8 + w;

    const uint4* Rv  = (const uint4*)(g_Rn + (size_t)row * NC) + lane;
    const float4* XSv = (const float4*)(g_Xsum + (row >> 10) * NC) + lane * 2;

    uint4  rv = *Rv;
    float4 x0 = XSv[0];
    float4 x1 = XSv[1];

    const __nv_bfloat162* rp = (const __nv_bfloat162*)&rv;
    float d = 0.0f;
    float2 p;
    p = __bfloat1622float2(rp[0]); d = fmaf(p.x, x0.x, d); d = fmaf(p.y, x0.y, d);
    p = __bfloat1622float2(rp[1]); d = fmaf(p.x, x0.z, d); d = fmaf(p.y, x0.w, d);
    p = __bfloat1622float2(rp[2]); d = fmaf(p.x, x1.x, d); d = fmaf(p.y, x1.y, d);
    p = __bfloat1622float2(rp[3]); d = fmaf(p.x, x1.z, d); d = fmaf(p.y, x1.w, d);

    #pragma unroll
    for (int o = 16; o; o >>= 1) d += __shfl_xor_sync(0xffffffffu, d, o);

    if (lane == 0) {
        float contrib = 1024.0f * logf(g_rowsum[row]) - d * INV_T;
        atomicAdd(&g_acc, (double)contrib);
    }
}

// ---------------- final scalar -------------------------------------------
__global__ void k_out(float* __restrict__ out) {
    out[0] = (float)(g_acc / (POS_COUNT + 1e-8));
}

extern "C" void kernel_launch(void* const* d_in, const int* in_sizes, int n_in,
                              void* d_out, int out_size) {
    const float* rgb = (const float*)d_in[0];
    const float* x   = (const float*)d_in[1];
    float* out = (float*)d_out;
    (void)in_sizes; (void)n_in; (void)out_size;

    const int GEMM_SMEM = 3 * 32 * 132 * 4;   // 50688 bytes
    cudaFuncSetAttribute(k_gemm, cudaFuncAttributeMaxDynamicSharedMemorySize, GEMM_SMEM);

    k_init<<<40, 256>>>();
    k_norm<<<512, 256>>>(rgb, x);
    k_gemm<<<512, 256, GEMM_SMEM>>>();
    k_row<<<1024, 256>>>();
    k_out<<<1, 1>>>(out);
}

// round 6
// speedup vs baseline: 1.0671x; 1.0671x over previous
#include <cuda_runtime.h>
#include <cuda_bf16.h>
#include <math.h>
#include <stdint.h>

// Problem constants
#define NB 8
#define NC 256
#define NHW 1024
#define NROW 8192              // NB*NHW
#define INV_T 10.0f            // 1/TEMPERATURE
#define POS_COUNT 8388608.0    // 8192*1024

// ---------------- device scratch (no allocation allowed) ----------------
__device__ __align__(256) __nv_bfloat16 g_Rn[NROW * NC];   // normalized rgb
__device__ __align__(256) __nv_bfloat16 g_Xn[NROW * NC];   // normalized x
__device__ float  g_Xsum[8 * NC];           // per-class (j%8) column sums of normalized x
__device__ float  g_rowsum[NROW];           // sum_j exp(sim_ij)
__device__ double g_acc;                    // global loss accumulator
__device__ unsigned g_done;                 // k_row completion counter

__device__ __forceinline__ float ex2f(float x) {
    float r; asm("ex2.approx.f32 %0, %1;" : "=f"(r) : "f"(x)); return r;
}

// ---------------- init ---------------------------------------------------
__global__ void k_init() {
    int idx = blockIdx.x * blockDim.x + threadIdx.x;
    if (idx < NROW) g_rowsum[idx] = 0.0f;
    if (idx < 8 * NC) g_Xsum[idx] = 0.0f;
    if (idx == 0) { g_acc = 0.0; g_done = 0u; }
}

// ---------------- normalize (B,C,H,W) -> rows of 256, bf16 --------------
// grid 512: blocks [0,256) process rgb, [256,512) process x.
__global__ void __launch_bounds__(256) k_norm(const float* __restrict__ rgb,
                                              const float* __restrict__ x) {
    __shared__ float s[32][257];
    __shared__ float ps[8][32];
    __shared__ float invs[32];

    int tid = threadIdx.x;
    int isX = blockIdx.x >> 8;
    int bix = blockIdx.x & 255;
    int b   = bix >> 5;
    int p0  = (bix & 31) << 5;
    int pl  = tid & 31;
    int cg  = tid >> 5;

    const float* in = isX ? x : rgb;
    const float* base = in + (size_t)b * NC * NHW + p0;
    #pragma unroll
    for (int co = 0; co < 32; ++co) {
        int c = co * 8 + cg;
        s[pl][c] = base[(size_t)c * NHW + pl];
    }
    __syncthreads();

    float part = 0.0f;
    #pragma unroll
    for (int k = 0; k < 32; ++k) {
        float v = s[pl][cg * 32 + k];
        part = fmaf(v, v, part);
    }
    ps[cg][pl] = part;
    __syncthreads();

    if (tid < 32) {
        float ss = 0.0f;
        #pragma unroll
        for (int j = 0; j < 8; ++j) ss += ps[j][tid];
        invs[tid] = 1.0f / fmaxf(sqrtf(ss), 1e-12f);
    }
    __syncthreads();

    __nv_bfloat16* out = isX ? g_Xn : g_Rn;
    float xacc[8];
    #pragma unroll
    for (int m = 0; m < 8; ++m) xacc[m] = 0.0f;

    #pragma unroll
    for (int rl = 0; rl < 32; ++rl) {
        float v = s[rl][tid] * invs[rl];
        out[(size_t)(b * NHW + p0 + rl) * NC + tid] = __float2bfloat16(v);
        xacc[rl & 7] += v;
    }
    if (isX) {
        #pragma unroll
        for (int m = 0; m < 8; ++m)
            atomicAdd(&g_Xsum[m * NC + tid], xacc[m]);
    }
}

// ---------------- helpers for the GEMM ----------------------------------
__device__ __forceinline__ void mma16816(float c[4], const uint32_t a[4],
                                         uint32_t b0, uint32_t b1) {
    asm volatile(
        "mma.sync.aligned.m16n8k16.row.col.f32.bf16.bf16.f32 "
        "{%0,%1,%2,%3}, {%4,%5,%6,%7}, {%8,%9}, {%0,%1,%2,%3};"
        : "+f"(c[0]), "+f"(c[1]), "+f"(c[2]), "+f"(c[3])
        : "r"(a[0]), "r"(a[1]), "r"(a[2]), "r"(a[3]), "r"(b0), "r"(b1));
}

// issue 64x256 bf16 tile load (32KB) via cp.async, one commit group
__device__ __forceinline__ void issue_load64(uint32_t dst_base,
                                             const __nv_bfloat16* src_base,
                                             int w, int lane) {
    const char* src = (const char*)src_base + lane * 16;
    #pragma unroll
    for (int it = 0; it < 8; ++it) {
        int row = it * 8 + w;
        uint32_t dst = dst_base + (uint32_t)(row * 132 + lane * 4) * 4;
        asm volatile("cp.async.cg.shared.global [%0], [%1], 16;"
                     :: "r"(dst), "l"(src + (size_t)row * 512) : "memory");
    }
    asm volatile("cp.async.commit_group;" ::: "memory");
}

// ---------------- fused GEMM + exp row-sum ------------------------------
// 512 blocks: 64 row-blocks (128 rows) x 8 column slices (1024 cols).
// Per CTA: 16 B-tiles of 64 cols, 3-stage cp.async pipeline (1 sync/tile).
// 8 warps; warp owns 16 rows; A register-resident for full K=256.
// 2 CTAs/SM (regs capped at 128); accumulators reused across 32-col halves.
__global__ void __launch_bounds__(256, 2) k_gemm() {
    extern __shared__ uint32_t Xs[];   // 3 buffers of 64*132 words

    int tid  = threadIdx.x;
    int w    = tid >> 5;
    int lane = tid & 31;
    int g    = lane >> 2;
    int tig  = lane & 3;

    int rowBlk = blockIdx.x & 63;
    int cslice = blockIdx.x >> 6;          // 0..7
    int r0     = rowBlk * 128;
    int cstart = cslice * 1024;

    int rg = r0 + w * 16 + g;
    const __nv_bfloat16* Ra = g_Rn + (size_t)rg * NC;
    const __nv_bfloat16* Rb = g_Rn + (size_t)(rg + 8) * NC;

    // A fragments for full K=256
    uint32_t a[16][4];
    #pragma unroll
    for (int kc = 0; kc < 16; ++kc) {
        a[kc][0] = *(const uint32_t*)(Ra + kc * 16 + 2 * tig);
        a[kc][1] = *(const uint32_t*)(Rb + kc * 16 + 2 * tig);
        a[kc][2] = *(const uint32_t*)(Ra + kc * 16 + 8 + 2 * tig);
        a[kc][3] = *(const uint32_t*)(Rb + kc * 16 + 8 + 2 * tig);
    }

    // ldmatrix per-lane offset (q=0, kc=0), in words
    int mi = lane >> 3, rr = lane & 7;
    int ldsm_off = (((mi >> 1) * 8) + rr) * 132 + (mi & 1) * 4;

    uint32_t sbase = (uint32_t)__cvta_generic_to_shared(Xs);
    const uint32_t BUFW = 64u * 132u * 4u;

    float rs0 = 0.0f, rs1 = 0.0f;
    const float S = 14.426950408889634f;   // log2(e)/0.1

    const __nv_bfloat16* xb = g_Xn + (size_t)cstart * NC;
    issue_load64(sbase,        xb,           w, lane);
    issue_load64(sbase + BUFW, xb + 64 * NC, w, lane);

    #pragma unroll 1
    for (int nt = 0; nt < 16; ++nt) {
        if (nt < 15) {
            asm volatile("cp.async.wait_group 1;" ::: "memory");
        } else {
            asm volatile("cp.async.wait_group 0;" ::: "memory");
        }
        __syncthreads();   // all warps done with iter nt-1; buf (nt+2)%3 free; buf nt%3 visible
        if (nt + 2 < 16)
            issue_load64(sbase + (uint32_t)((nt + 2) % 3) * BUFW,
                         xb + (size_t)(nt + 2) * 64 * NC, w, lane);

        uint32_t tile_base = sbase + (uint32_t)(nt % 3) * BUFW + (uint32_t)ldsm_off * 4;

        #pragma unroll
        for (int half = 0; half < 2; ++half) {
            float c[4][4];
            #pragma unroll
            for (int n8 = 0; n8 < 4; ++n8) {
                c[n8][0] = 0.f; c[n8][1] = 0.f; c[n8][2] = 0.f; c[n8][3] = 0.f;
            }
            uint32_t ld_base = tile_base + (uint32_t)(half * 2 * 2112) * 4;
            #pragma unroll
            for (int kc = 0; kc < 16; ++kc) {
                #pragma unroll
                for (int q = 0; q < 2; ++q) {
                    uint32_t b0, b1, b2, b3;
                    uint32_t ad = ld_base + (uint32_t)(q * 2112 + kc * 8) * 4;
                    asm volatile(
                        "ldmatrix.sync.aligned.m8n8.x4.shared.b16 {%0,%1,%2,%3}, [%4];"
                        : "=r"(b0), "=r"(b1), "=r"(b2), "=r"(b3) : "r"(ad));
                    mma16816(c[2 * q],     a[kc], b0, b1);
                    mma16816(c[2 * q + 1], a[kc], b2, b3);
                }
            }
            #pragma unroll
            for (int n8 = 0; n8 < 4; ++n8) {
                rs0 += ex2f(c[n8][0] * S) + ex2f(c[n8][1] * S);
                rs1 += ex2f(c[n8][2] * S) + ex2f(c[n8][3] * S);
            }
        }
    }

    rs0 += __shfl_xor_sync(0xffffffffu, rs0, 1);
    rs0 += __shfl_xor_sync(0xffffffffu, rs0, 2);
    rs1 += __shfl_xor_sync(0xffffffffu, rs1, 1);
    rs1 += __shfl_xor_sync(0xffffffffu, rs1, 2);
    if (tig == 0) {
        atomicAdd(&g_rowsum[rg], rs0);
        atomicAdd(&g_rowsum[rg + 8], rs1);
    }
}

// ---------------- per-row: 1024*log(rowsum) - posdot/T ------------------
// warp per row, block-level reduce, ONE double atomic per block;
// last block writes the final scalar (k_out fused).
__global__ void __launch_bounds__(256) k_row(float* __restrict__ out) {
    __shared__ float wsum[8];
    int tid  = threadIdx.x;
    int lane = tid & 31;
    int w    = tid >> 5;
    int row  = blockIdx.x * 8 + w;

    const uint4* Rv   = (const uint4*)(g_Rn + (size_t)row * NC) + lane;
    const float4* XSv = (const float4*)(g_Xsum + (row >> 10) * NC) + lane * 2;

    uint4  rv = *Rv;
    float4 x0 = XSv[0];
    float4 x1 = XSv[1];

    const __nv_bfloat162* rp = (const __nv_bfloat162*)&rv;
    float d = 0.0f;
    float2 p;
    p = __bfloat1622float2(rp[0]); d = fmaf(p.x, x0.x, d); d = fmaf(p.y, x0.y, d);
    p = __bfloat1622float2(rp[1]); d = fmaf(p.x, x0.z, d); d = fmaf(p.y, x0.w, d);
    p = __bfloat1622float2(rp[2]); d = fmaf(p.x, x1.x, d); d = fmaf(p.y, x1.y, d);
    p = __bfloat1622float2(rp[3]); d = fmaf(p.x, x1.z, d); d = fmaf(p.y, x1.w, d);

    #pragma unroll
    for (int o = 16; o; o >>= 1) d += __shfl_xor_sync(0xffffffffu, d, o);

    if (lane == 0)
        wsum[w] = 1024.0f * logf(g_rowsum[row]) - d * INV_T;
    __syncthreads();

    if (tid == 0) {
        float bs = 0.0f;
        #pragma unroll
        for (int j = 0; j < 8; ++j) bs += wsum[j];
        atomicAdd(&g_acc, (double)bs);
        __threadfence();
        unsigned t = atomicAdd(&g_done, 1u);
        if (t == gridDim.x - 1) {
            out[0] = (float)(g_acc / (POS_COUNT + 1e-8));
        }
    }
}

extern "C" void kernel_launch(void* const* d_in, const int* in_sizes, int n_in,
                              void* d_out, int out_size) {
    const float* rgb = (const float*)d_in[0];
    const float* x   = (const float*)d_in[1];
    float* out = (float*)d_out;
    (void)in_sizes; (void)n_in; (void)out_size;

    const int GEMM_SMEM = 3 * 64 * 132 * 4;   // 101376 bytes
    cudaFuncSetAttribute(k_gemm, cudaFuncAttributeMaxDynamicSharedMemorySize, GEMM_SMEM);

    k_init<<<40, 256>>>();
    k_norm<<<512, 256>>>(rgb, x);
    k_gemm<<<512, 256, GEMM_SMEM>>>();
    k_row<<<1024, 256>>>(out);
}